// round 3
// baseline (speedup 1.0000x reference)
#include <cuda_runtime.h>
#include <cuda_bf16.h>
#include <cstdint>

// ---------------- problem constants ----------------
#define NW   2048
#define TC   12
#define TS   4
#define CD   64
#define SD   64
#define WD   256
#define HH   128
#define Hd   256      // H
#define G    512      // 4*HH
#define XW   768      // WD + 2*H
#define NPOS 47
#define NNER 13

// ---------------- scratch (device globals; no allocs allowed) ----------------
__device__ float g_x_char[NW * TC * CD];
__device__ float g_x_syl[NW * TS * SD];
__device__ float g_gin_char[2 * NW * TC * G];
__device__ float g_gin_syl[2 * NW * TS * G];
__device__ float g_gin_word[2 * NW * G];
__device__ float g_out_char[TC * NW * Hd];
__device__ float g_out_syl[TS * NW * Hd];
__device__ float g_h[2 * NW * HH];
__device__ float g_c[2 * NW * HH];
__device__ float g_h0[2 * NW * HH];
__device__ float g_gates[2 * NW * G];
__device__ float g_logits_char[TC * NW];
__device__ float g_logits_syl[TS * NW];
__device__ float g_xword[NW * XW];
__device__ float g_outword[NW * Hd];

// ---------------- math helpers ----------------
__device__ __forceinline__ float sigf(float x) { return 1.0f / (1.0f + __expf(-x)); }
__device__ __forceinline__ float tanhfast(float x) {
    float t = __expf(-2.0f * fabsf(x));
    float r = (1.0f - t) / (1.0f + t);
    return copysignf(r, x);
}
__device__ __forceinline__ uint32_t smem_u32(const void* p) {
    uint32_t a;
    asm("{ .reg .u64 t; cvta.to.shared.u64 t, %1; cvt.u32.u64 %0, t; }" : "=r"(a) : "l"(p));
    return a;
}

// ---------------- gather: embeddings + h0 init ----------------
__global__ void gather_kernel(const int* __restrict__ word_seq, const int* __restrict__ syl_seq,
                              const int* __restrict__ char_seq, const int* __restrict__ feat_seq,
                              const float* __restrict__ emb_char, const float* __restrict__ emb_syl,
                              const float* __restrict__ emb_word, const float* __restrict__ emb_prefix) {
    int idx = blockIdx.x * blockDim.x + threadIdx.x;
    const int n0 = NW * TC * CD;
    const int n1 = n0 + NW * TS * SD;
    const int n2 = n1 + 2 * NW * HH;
    const int n3 = n2 + NW * WD;
    if (idx < n0) {
        int d = idx % CD; int rest = idx / CD; int t = rest % TC; int w = rest / TC;
        g_x_char[idx] = emb_char[char_seq[w * TC + t] * CD + d];
    } else if (idx < n1) {
        int i = idx - n0;
        int d = i % SD; int rest = i / SD; int t = rest % TS; int w = rest / TS;
        g_x_syl[i] = emb_syl[syl_seq[w * TS + t] * SD + d];
    } else if (idx < n2) {
        int i = idx - n1;             // [dir][w][j]
        int j = i % HH; int rest = i / HH; int w = rest % NW; int dir = rest / NW;
        float v = emb_prefix[feat_seq[w] * Hd + dir * HH + j];
        g_h0[i] = v; g_h[i] = v; g_c[i] = 0.0f;
    } else if (idx < n3) {
        int i = idx - n2;
        int d = i % WD; int w = i / WD;
        g_xword[w * XW + d] = emb_word[word_seq[w] * WD + d];
    }
}

__global__ void clear_logits_kernel() {
    int idx = blockIdx.x * blockDim.x + threadIdx.x;
    if (idx < TC * NW) g_logits_char[idx] = 0.0f;
    if (idx < TS * NW) g_logits_syl[idx] = 0.0f;
}

__global__ void reinit_state_kernel() {
    int idx = blockIdx.x * blockDim.x + threadIdx.x;
    if (idx < 2 * NW * HH) { g_h[idx] = g_h0[idx]; g_c[idx] = 0.0f; }
}

// ---------------- generic tiled GEMM (double-buffered):  C = A[M,K] @ B[N,K]^T (+Add)(+b1+b2) ----
#define BMt 64
#define BNt 64
#define BKt 16

__global__ void __launch_bounds__(256) gemm64(
    const float* __restrict__ A, long long sAz,
    const float* __restrict__ B, long long sBz,
    const float* __restrict__ Add, long long sAddz, int ldAdd,
    const float* __restrict__ b1, const float* __restrict__ b2, long long sbz,
    float* __restrict__ C, long long sCz,
    int M, int N, int K) {
    __shared__ float As[2][BKt][BMt];
    __shared__ float Bs[2][BKt][BNt];
    long long z = blockIdx.z;
    A += z * sAz; B += z * sBz; C += z * sCz;
    if (Add) Add += z * sAddz;
    if (b1) b1 += z * sbz;
    if (b2) b2 += z * sbz;

    int tid = threadIdx.x;
    int bm = blockIdx.y * BMt, bn = blockIdx.x * BNt;
    int ar = tid >> 2, ak = (tid & 3) << 2;
    int ty = tid >> 4, tx = tid & 15;
    float acc[4][4] = {};

    // prologue: load tile 0
    {
        float4 av = *(const float4*)(A + (size_t)(bm + ar) * K + ak);
        float4 bv = *(const float4*)(B + (size_t)(bn + ar) * K + ak);
        As[0][ak + 0][ar] = av.x; As[0][ak + 1][ar] = av.y; As[0][ak + 2][ar] = av.z; As[0][ak + 3][ar] = av.w;
        Bs[0][ak + 0][ar] = bv.x; Bs[0][ak + 1][ar] = bv.y; Bs[0][ak + 2][ar] = bv.z; Bs[0][ak + 3][ar] = bv.w;
    }
    __syncthreads();

    int ntiles = K / BKt;
    for (int kt = 0; kt < ntiles; kt++) {
        int buf = kt & 1;
        float4 a2, b2v;
        bool more = (kt + 1 < ntiles);
        if (more) {
            a2  = *(const float4*)(A + (size_t)(bm + ar) * K + (kt + 1) * BKt + ak);
            b2v = *(const float4*)(B + (size_t)(bn + ar) * K + (kt + 1) * BKt + ak);
        }
#pragma unroll
        for (int kk = 0; kk < BKt; kk++) {
            float4 a = *(const float4*)&As[buf][kk][ty << 2];
            float4 b = *(const float4*)&Bs[buf][kk][tx << 2];
            float ar4[4] = {a.x, a.y, a.z, a.w};
            float br4[4] = {b.x, b.y, b.z, b.w};
#pragma unroll
            for (int i = 0; i < 4; i++)
#pragma unroll
                for (int j = 0; j < 4; j++)
                    acc[i][j] = fmaf(ar4[i], br4[j], acc[i][j]);
        }
        if (more) {
            int nb = buf ^ 1;
            As[nb][ak + 0][ar] = a2.x;  As[nb][ak + 1][ar] = a2.y;  As[nb][ak + 2][ar] = a2.z;  As[nb][ak + 3][ar] = a2.w;
            Bs[nb][ak + 0][ar] = b2v.x; Bs[nb][ak + 1][ar] = b2v.y; Bs[nb][ak + 2][ar] = b2v.z; Bs[nb][ak + 3][ar] = b2v.w;
        }
        __syncthreads();
    }
#pragma unroll
    for (int i = 0; i < 4; i++) {
        int m = bm + (ty << 2) + i;
#pragma unroll
        for (int j = 0; j < 4; j++) {
            int n = bn + (tx << 2) + j;
            float v = acc[i][j];
            if (b1) v += b1[n];
            if (b2) v += b2[n];
            if (Add) v += Add[(size_t)m * ldAdd + n];
            C[(size_t)m * N + n] = v;
        }
    }
}

// ---------------- attention GEMM: logits[m] += sum_n tanh(A@B^T + ba)[m,n]*wv[n] ----------------
__global__ void __launch_bounds__(256) gemm_attn(
    const float* __restrict__ A, const float* __restrict__ B,
    const float* __restrict__ ba, const float* __restrict__ wv,
    float* __restrict__ logits, int M, int K) {
    __shared__ float As[2][BKt][BMt];
    __shared__ float Bs[2][BKt][BNt];
    int tid = threadIdx.x;
    int bm = blockIdx.y * BMt, bn = blockIdx.x * BNt;
    int ar = tid >> 2, ak = (tid & 3) << 2;
    int ty = tid >> 4, tx = tid & 15;
    float acc[4][4] = {};
    {
        float4 av = *(const float4*)(A + (size_t)(bm + ar) * K + ak);
        float4 bv = *(const float4*)(B + (size_t)(bn + ar) * K + ak);
        As[0][ak + 0][ar] = av.x; As[0][ak + 1][ar] = av.y; As[0][ak + 2][ar] = av.z; As[0][ak + 3][ar] = av.w;
        Bs[0][ak + 0][ar] = bv.x; Bs[0][ak + 1][ar] = bv.y; Bs[0][ak + 2][ar] = bv.z; Bs[0][ak + 3][ar] = bv.w;
    }
    __syncthreads();
    int ntiles = K / BKt;
    for (int kt = 0; kt < ntiles; kt++) {
        int buf = kt & 1;
        float4 a2, b2v;
        bool more = (kt + 1 < ntiles);
        if (more) {
            a2  = *(const float4*)(A + (size_t)(bm + ar) * K + (kt + 1) * BKt + ak);
            b2v = *(const float4*)(B + (size_t)(bn + ar) * K + (kt + 1) * BKt + ak);
        }
#pragma unroll
        for (int kk = 0; kk < BKt; kk++) {
            float4 a = *(const float4*)&As[buf][kk][ty << 2];
            float4 b = *(const float4*)&Bs[buf][kk][tx << 2];
            float ar4[4] = {a.x, a.y, a.z, a.w};
            float br4[4] = {b.x, b.y, b.z, b.w};
#pragma unroll
            for (int i = 0; i < 4; i++)
#pragma unroll
                for (int j = 0; j < 4; j++)
                    acc[i][j] = fmaf(ar4[i], br4[j], acc[i][j]);
        }
        if (more) {
            int nb = buf ^ 1;
            As[nb][ak + 0][ar] = a2.x;  As[nb][ak + 1][ar] = a2.y;  As[nb][ak + 2][ar] = a2.z;  As[nb][ak + 3][ar] = a2.w;
            Bs[nb][ak + 0][ar] = b2v.x; Bs[nb][ak + 1][ar] = b2v.y; Bs[nb][ak + 2][ar] = b2v.z; Bs[nb][ak + 3][ar] = b2v.w;
        }
        __syncthreads();
    }
#pragma unroll
    for (int i = 0; i < 4; i++) {
        float s = 0.0f;
#pragma unroll
        for (int j = 0; j < 4; j++) {
            int n = bn + (tx << 2) + j;
            s += tanhfast(acc[i][j] + ba[n]) * wv[n];
        }
        s += __shfl_down_sync(0xffffffffu, s, 8, 16);
        s += __shfl_down_sync(0xffffffffu, s, 4, 16);
        s += __shfl_down_sync(0xffffffffu, s, 2, 16);
        s += __shfl_down_sync(0xffffffffu, s, 1, 16);
        if (tx == 0) atomicAdd(&logits[bm + (ty << 2) + i], s);
    }
}

// ---------------- LSTM pointwise: gates -> (h,c), writes out_seq[t][w][dir*HH+j] ----------------
__global__ void lstm_pointwise(float* __restrict__ out_seq, int s, int T) {
    int idx = blockIdx.x * blockDim.x + threadIdx.x;
    if (idx >= 2 * NW * HH) return;
    int j = idx % HH; int rest = idx / HH; int w = rest % NW; int dir = rest / NW;
    const float* g = g_gates + ((size_t)dir * NW + w) * G;
    float gi = sigf(g[j]);
    float gf = sigf(g[HH + j]);
    float gg = tanhfast(g[2 * HH + j]);
    float go = sigf(g[3 * HH + j]);
    float c = gf * g_c[idx] + gi * gg;
    float h = go * tanhfast(c);
    g_c[idx] = c; g_h[idx] = h;
    int t = dir ? (T - 1 - s) : s;
    out_seq[((size_t)t * NW + w) * Hd + dir * HH + j] = h;
}

// ---------------- attention softmax over t + context accumulation ----------------
__global__ void attn_ctx(const float* __restrict__ logits, const float* __restrict__ out_seq,
                         int T, int off) {
    int w = blockIdx.x;
    int tid = threadIdx.x;   // 256 = H
    __shared__ float p[16];
    if (tid == 0) {
        float l[16];
        float mx = -1e30f;
        for (int t = 0; t < T; t++) { l[t] = logits[t * NW + w]; mx = fmaxf(mx, l[t]); }
        float s = 0.0f;
        for (int t = 0; t < T; t++) { float e = __expf(l[t] - mx); p[t] = e; s += e; }
        float inv = 1.0f / s;
        for (int t = 0; t < T; t++) p[t] *= inv;
    }
    __syncthreads();
    float acc = 0.0f;
    for (int t = 0; t < T; t++)
        acc += p[t] * out_seq[((size_t)t * NW + w) * Hd + tid];
    g_xword[(size_t)w * XW + off + tid] = acc;
}

// ---------------- cluster-parallel word-level BiLSTM (batch=1, T=2048, sequential) ----------------
// 2 directions x 4-CTA cluster. Each CTA owns 32 h-outputs (128 gate rows),
// Whh slice fully in registers. Handoff: weak DSMEM stores by 32 producers,
// __syncwarp, then ONE elected thread: fence.acq_rel.cluster + 1 arrive per dest CTA
// (barrier arrive count = 4). Double-buffered h + barrier pair with explicit parity.
#define WCL 4

__global__ void __launch_bounds__(512, 1) __cluster_dims__(WCL, 1, 1)
word_lstm_cluster(const float* __restrict__ Whh) {
    __shared__ float hbuf[2][HH];
    __shared__ float gsm[128];
    __shared__ __align__(16) unsigned long long mbar[2];

    int tid = threadIdx.x;
    int dir = blockIdx.x / WCL;
    uint32_t crank;
    asm("mov.u32 %0, %%cluster_ctarank;" : "=r"(crank));
    int r = tid >> 2, p = tid & 3;        // row 0..127, k-part 0..3
    int gate = r >> 5, jj = r & 31;
    int jbase = (int)crank * 32;
    int n = gate * 128 + jbase + jj;       // global gate row

    // weights: k interleaved (thread p owns k = 4m+p)
    const float* W = Whh + (size_t)dir * (G * HH) + (size_t)n * HH;
    float wreg[32];
#pragma unroll
    for (int m = 0; m < 32; m++) wreg[m] = W[4 * m + p];

    if (tid < HH) { hbuf[0][tid] = 0.0f; hbuf[1][tid] = 0.0f; }
    uint32_t mb_a[2];
    mb_a[0] = smem_u32((const void*)&mbar[0]);
    mb_a[1] = smem_u32((const void*)&mbar[1]);
    if (tid == 0) {
        asm volatile("mbarrier.init.shared.b64 [%0], %1;" :: "r"(mb_a[0]), "r"((uint32_t)WCL) : "memory");
        asm volatile("mbarrier.init.shared.b64 [%0], %1;" :: "r"(mb_a[1]), "r"((uint32_t)WCL) : "memory");
    }
    __syncthreads();
    asm volatile("barrier.cluster.arrive.aligned;" ::: "memory");
    asm volatile("barrier.cluster.wait.aligned;" ::: "memory");

    // remote smem addresses for all cluster ranks
    uint32_t hb_a = smem_u32((const void*)&hbuf[0][0]);
    uint32_t rem_h[WCL], rem_b0[WCL], rem_b1[WCL];
#pragma unroll
    for (int c = 0; c < WCL; c++) {
        asm("mapa.shared::cluster.u32 %0, %1, %2;" : "=r"(rem_h[c]) : "r"(hb_a), "r"(c));
        asm("mapa.shared::cluster.u32 %0, %1, %2;" : "=r"(rem_b0[c]) : "r"(mb_a[0]), "r"(c));
        asm("mapa.shared::cluster.u32 %0, %1, %2;" : "=r"(rem_b1[c]) : "r"(mb_a[1]), "r"(c));
    }

    const float* ginp = g_gin_word + (size_t)dir * NW * G + n;
    int t = dir ? (NW - 1) : 0;
    int tstep = dir ? -1 : 1;
    float ginv = (p == 0) ? __ldg(ginp + (size_t)t * G) : 0.0f;
    float creg = 0.0f;
    uint32_t par[2] = {0u, 0u};

    for (int s = 0; s < NW; s++, t += tstep) {
        if (s > 0) {
            int b = s & 1;
            asm volatile(
                "{\n\t.reg .pred P1;\n\t"
                "WL%=:\n\t"
                "mbarrier.try_wait.parity.acquire.cluster.shared::cta.b64 P1, [%0], %1, 0x989680;\n\t"
                "@P1 bra.uni WD%=;\n\t"
                "bra.uni WL%=;\n\t"
                "WD%=:\n\t}"
                :: "r"(mb_a[b]), "r"(par[b]) : "memory");
            par[b] ^= 1u;
        }
        const float* hs = hbuf[s & 1];
        float a0 = ginv, a1 = 0.0f, a2 = 0.0f, a3 = 0.0f;
        if (p == 0 && s + 1 < NW) ginv = __ldg(ginp + (size_t)(t + tstep) * G);  // prefetch
#pragma unroll
        for (int m = 0; m < 32; m += 4) {
            a0 = fmaf(wreg[m + 0], hs[4 * (m + 0) + p], a0);
            a1 = fmaf(wreg[m + 1], hs[4 * (m + 1) + p], a1);
            a2 = fmaf(wreg[m + 2], hs[4 * (m + 2) + p], a2);
            a3 = fmaf(wreg[m + 3], hs[4 * (m + 3) + p], a3);
        }
        float acc = (a0 + a1) + (a2 + a3);
        acc += __shfl_down_sync(0xffffffffu, acc, 2, 4);
        acc += __shfl_down_sync(0xffffffffu, acc, 1, 4);
        if (p == 0) {
            gsm[r] = (gate == 2) ? tanhfast(acc) : sigf(acc);
        }
        __syncthreads();   // also guarantees all threads finished reading hbuf[s&1]
        if (tid < 32) {
            float gi = gsm[tid], gf = gsm[32 + tid], gg = gsm[64 + tid], go = gsm[96 + tid];
            creg = gf * creg + gi * gg;
            float hh = go * tanhfast(creg);
            g_outword[(size_t)t * Hd + dir * HH + jbase + tid] = hh;
            if (s + 1 < NW) {
                int nb = (s + 1) & 1;
                uint32_t off = (uint32_t)(nb * HH + jbase + tid) * 4u;
#pragma unroll
                for (int c = 0; c < WCL; c++)
                    asm volatile("st.shared::cluster.f32 [%0], %1;"
                                 :: "r"(rem_h[c] + off), "f"(hh) : "memory");
                __syncwarp(0xffffffffu);
                if (tid == 0) {
                    asm volatile("fence.acq_rel.cluster;" ::: "memory");
                    if (nb) {
#pragma unroll
                        for (int c = 0; c < WCL; c++)
                            asm volatile("mbarrier.arrive.release.cluster.shared::cluster.b64 _, [%0];"
                                         :: "r"(rem_b1[c]) : "memory");
                    } else {
#pragma unroll
                        for (int c = 0; c < WCL; c++)
                            asm volatile("mbarrier.arrive.release.cluster.shared::cluster.b64 _, [%0];"
                                         :: "r"(rem_b0[c]) : "memory");
                    }
                }
            }
        }
    }
}

// ---------------- final linear + log_softmax ----------------
__global__ void tag_kernel(const float* __restrict__ Wp, const float* __restrict__ bp,
                           const float* __restrict__ Wn, const float* __restrict__ bn,
                           float* __restrict__ out) {
    int w = blockIdx.x;
    int tid = threadIdx.x;  // 64
    __shared__ float o[Hd];
    __shared__ float sc[64];
    __shared__ float sc2[16];
    __shared__ float zp, zn;
    for (int d = tid; d < Hd; d += 64) o[d] = g_outword[(size_t)w * Hd + d];
    __syncthreads();
    if (tid < NPOS) {
        float s = bp[tid];
        for (int k = 0; k < Hd; k++) s = fmaf(o[k], Wp[tid * Hd + k], s);
        sc[tid] = s;
    }
    if (tid < NNER) {
        float s = bn[tid];
        for (int k = 0; k < Hd; k++) s = fmaf(o[k], Wn[tid * Hd + k], s);
        sc2[tid] = s;
    }
    __syncthreads();
    if (tid == 0) {
        float m = -1e30f;
        for (int i = 0; i < NPOS; i++) m = fmaxf(m, sc[i]);
        float s = 0.0f;
        for (int i = 0; i < NPOS; i++) s += __expf(sc[i] - m);
        zp = m + logf(s);
    }
    if (tid == 1) {
        float m = -1e30f;
        for (int i = 0; i < NNER; i++) m = fmaxf(m, sc2[i]);
        float s = 0.0f;
        for (int i = 0; i < NNER; i++) s += __expf(sc2[i] - m);
        zn = m + logf(s);
    }
    __syncthreads();
    if (tid < NPOS) out[(size_t)w * NPOS + tid] = sc[tid] - zp;
    if (tid < NNER) out[(size_t)NW * NPOS + (size_t)w * NNER + tid] = sc2[tid] - zn;
}

// ---------------- host launch ----------------
extern "C" void kernel_launch(void* const* d_in, const int* in_sizes, int n_in,
                              void* d_out, int out_size) {
    const int* word_seq = (const int*)d_in[0];
    const int* syl_seq  = (const int*)d_in[1];
    const int* char_seq = (const int*)d_in[2];
    const int* feat_seq = (const int*)d_in[3];
    const float* emb_char   = (const float*)d_in[4];
    const float* emb_syl    = (const float*)d_in[5];
    const float* emb_word   = (const float*)d_in[6];
    const float* emb_prefix = (const float*)d_in[7];
    const float* attn_c_W = (const float*)d_in[8];
    const float* attn_c_b = (const float*)d_in[9];
    const float* attn_c_w = (const float*)d_in[10];
    const float* attn_s_W = (const float*)d_in[11];
    const float* attn_s_b = (const float*)d_in[12];
    const float* attn_s_w = (const float*)d_in[13];
    const float* Wih_c = (const float*)d_in[14];
    const float* Whh_c = (const float*)d_in[15];
    const float* bih_c = (const float*)d_in[16];
    const float* bhh_c = (const float*)d_in[17];
    const float* Wih_s = (const float*)d_in[18];
    const float* Whh_s = (const float*)d_in[19];
    const float* bih_s = (const float*)d_in[20];
    const float* bhh_s = (const float*)d_in[21];
    const float* Wih_w = (const float*)d_in[22];
    const float* Whh_w = (const float*)d_in[23];
    const float* bih_w = (const float*)d_in[24];
    const float* bhh_w = (const float*)d_in[25];
    const float* W_pos = (const float*)d_in[26];
    const float* b_pos = (const float*)d_in[27];
    const float* W_ner = (const float*)d_in[28];
    const float* b_ner = (const float*)d_in[29];
    float* out = (float*)d_out;

    float *p_x_char, *p_x_syl, *p_gin_char, *p_gin_syl, *p_gin_word;
    float *p_out_char, *p_out_syl, *p_h, *p_gates, *p_lg_char, *p_lg_syl, *p_xword;
    cudaGetSymbolAddress((void**)&p_x_char, g_x_char);
    cudaGetSymbolAddress((void**)&p_x_syl, g_x_syl);
    cudaGetSymbolAddress((void**)&p_gin_char, g_gin_char);
    cudaGetSymbolAddress((void**)&p_gin_syl, g_gin_syl);
    cudaGetSymbolAddress((void**)&p_gin_word, g_gin_word);
    cudaGetSymbolAddress((void**)&p_out_char, g_out_char);
    cudaGetSymbolAddress((void**)&p_out_syl, g_out_syl);
    cudaGetSymbolAddress((void**)&p_h, g_h);
    cudaGetSymbolAddress((void**)&p_gates, g_gates);
    cudaGetSymbolAddress((void**)&p_lg_char, g_logits_char);
    cudaGetSymbolAddress((void**)&p_lg_syl, g_logits_syl);
    cudaGetSymbolAddress((void**)&p_xword, g_xword);

    // 0) clear attention logits
    clear_logits_kernel<<<(TC * NW + 255) / 256, 256>>>();
    // 1) embedding gathers + h0/c0 init
    {
        int total = NW * TC * CD + NW * TS * SD + 2 * NW * HH + NW * WD;
        gather_kernel<<<(total + 255) / 256, 256>>>(word_seq, syl_seq, char_seq, feat_seq,
                                                    emb_char, emb_syl, emb_word, emb_prefix);
    }
    // 2) input projections (Gin = x @ Wih^T + bih + bhh) for char & syl, both dirs
    gemm64<<<dim3(G / 64, (NW * TC) / 64, 2), 256>>>(
        p_x_char, 0, Wih_c, (long long)G * CD,
        nullptr, 0, 0, bih_c, bhh_c, G,
        p_gin_char, (long long)NW * TC * G, NW * TC, G, CD);
    gemm64<<<dim3(G / 64, (NW * TS) / 64, 2), 256>>>(
        p_x_syl, 0, Wih_s, (long long)G * SD,
        nullptr, 0, 0, bih_s, bhh_s, G,
        p_gin_syl, (long long)NW * TS * G, NW * TS, G, SD);

    // 3) char BiLSTM recurrence (12 steps, both dirs per launch)
    for (int s = 0; s < TC; s++) {
        gemm64<<<dim3(G / 64, NW / 64, 2), 256>>>(
            p_h, (long long)NW * HH, Whh_c, (long long)G * HH,
            p_gin_char + (size_t)s * G,
            (long long)NW * TC * G + (long long)(TC - 1 - 2 * s) * G, TC * G,
            nullptr, nullptr, 0,
            p_gates, (long long)NW * G, NW, G, HH);
        lstm_pointwise<<<(2 * NW * HH + 255) / 256, 256>>>(p_out_char, s, TC);
    }
    // 4) char attention -> char_ctx into xword[:,256:512]
    gemm_attn<<<dim3(Hd / 64, (TC * NW) / 64), 256>>>(p_out_char, attn_c_W, attn_c_b, attn_c_w,
                                                      p_lg_char, TC * NW, Hd);
    attn_ctx<<<NW, Hd>>>(p_lg_char, p_out_char, TC, WD);

    // 5) syl BiLSTM (reinit state from h0, c=0)
    reinit_state_kernel<<<(2 * NW * HH + 255) / 256, 256>>>();
    for (int s = 0; s < TS; s++) {
        gemm64<<<dim3(G / 64, NW / 64, 2), 256>>>(
            p_h, (long long)NW * HH, Whh_s, (long long)G * HH,
            p_gin_syl + (size_t)s * G,
            (long long)NW * TS * G + (long long)(TS - 1 - 2 * s) * G, TS * G,
            nullptr, nullptr, 0,
            p_gates, (long long)NW * G, NW, G, HH);
        lstm_pointwise<<<(2 * NW * HH + 255) / 256, 256>>>(p_out_syl, s, TS);
    }
    // 6) syl attention -> syl_ctx into xword[:,512:768]
    gemm_attn<<<dim3(Hd / 64, (TS * NW) / 64), 256>>>(p_out_syl, attn_s_W, attn_s_b, attn_s_w,
                                                      p_lg_syl, TS * NW, Hd);
    attn_ctx<<<NW, Hd>>>(p_lg_syl, p_out_syl, TS, WD + Hd);

    // 7) word-level input projection
    gemm64<<<dim3(G / 64, NW / 64, 2), 256>>>(
        p_xword, 0, Wih_w, (long long)G * XW,
        nullptr, 0, 0, bih_w, bhh_w, G,
        p_gin_word, (long long)NW * G, NW, G, XW);

    // 8) sequential word BiLSTM: 2 directions x 4-CTA cluster
    word_lstm_cluster<<<2 * WCL, 512>>>(Whh_w);

    // 9) final linear + log_softmax -> [pos(2048x47) | ner(2048x13)]
    tag_kernel<<<NW, 64>>>(W_pos, b_pos, W_ner, b_ner, out);
}

// round 5
// speedup vs baseline: 1.6803x; 1.6803x over previous
#include <cuda_runtime.h>
#include <cuda_bf16.h>
#include <cstdint>

// ---------------- problem constants ----------------
#define NW   2048
#define TC   12
#define TS   4
#define CD   64
#define SD   64
#define WD   256
#define HH   128
#define Hd   256      // H
#define G    512      // 4*HH
#define XW   768      // WD + 2*H
#define NPOS 47
#define NNER 13

// ---------------- scratch (device globals; no allocs allowed) ----------------
__device__ float g_x_char[NW * TC * CD];
__device__ float g_x_syl[NW * TS * SD];
__device__ float g_gin_char[2 * NW * TC * G];
__device__ float g_gin_syl[2 * NW * TS * G];
__device__ float g_gin_word[2 * NW * G];
__device__ float g_out_char[TC * NW * Hd];
__device__ float g_out_syl[TS * NW * Hd];
__device__ float g_h[2 * NW * HH];
__device__ float g_c[2 * NW * HH];
__device__ float g_h0[2 * NW * HH];
__device__ float g_gates[2 * NW * G];
__device__ float g_logits_char[TC * NW];
__device__ float g_logits_syl[TS * NW];
__device__ float g_xword[NW * XW];
__device__ float g_outword[NW * Hd];

// ---------------- math helpers ----------------
__device__ __forceinline__ float sigf(float x) { return 1.0f / (1.0f + __expf(-x)); }
__device__ __forceinline__ float tanhfast(float x) {
    float t = __expf(-2.0f * fabsf(x));
    float r = (1.0f - t) / (1.0f + t);
    return copysignf(r, x);
}
__device__ __forceinline__ uint32_t smem_u32(const void* p) {
    uint32_t a;
    asm("{ .reg .u64 t; cvta.to.shared.u64 t, %1; cvt.u32.u64 %0, t; }" : "=r"(a) : "l"(p));
    return a;
}
__device__ __forceinline__ void fma2(unsigned long long& d, unsigned long long a, unsigned long long b) {
    asm("fma.rn.f32x2 %0, %1, %2, %0;" : "+l"(d) : "l"(a), "l"(b));
}
__device__ __forceinline__ float upsum(unsigned long long a) {
    return __uint_as_float((uint32_t)a) + __uint_as_float((uint32_t)(a >> 32));
}

// ---------------- gather: embeddings + h0 init ----------------
__global__ void gather_kernel(const int* __restrict__ word_seq, const int* __restrict__ syl_seq,
                              const int* __restrict__ char_seq, const int* __restrict__ feat_seq,
                              const float* __restrict__ emb_char, const float* __restrict__ emb_syl,
                              const float* __restrict__ emb_word, const float* __restrict__ emb_prefix) {
    int idx = blockIdx.x * blockDim.x + threadIdx.x;
    const int n0 = NW * TC * CD;
    const int n1 = n0 + NW * TS * SD;
    const int n2 = n1 + 2 * NW * HH;
    const int n3 = n2 + NW * WD;
    if (idx < n0) {
        int d = idx % CD; int rest = idx / CD; int t = rest % TC; int w = rest / TC;
        g_x_char[idx] = emb_char[char_seq[w * TC + t] * CD + d];
    } else if (idx < n1) {
        int i = idx - n0;
        int d = i % SD; int rest = i / SD; int t = rest % TS; int w = rest / TS;
        g_x_syl[i] = emb_syl[syl_seq[w * TS + t] * SD + d];
    } else if (idx < n2) {
        int i = idx - n1;             // [dir][w][j]
        int j = i % HH; int rest = i / HH; int w = rest % NW; int dir = rest / NW;
        float v = emb_prefix[feat_seq[w] * Hd + dir * HH + j];
        g_h0[i] = v; g_h[i] = v; g_c[i] = 0.0f;
    } else if (idx < n3) {
        int i = idx - n2;
        int d = i % WD; int w = i / WD;
        g_xword[w * XW + d] = emb_word[word_seq[w] * WD + d];
    }
}

__global__ void clear_logits_kernel() {
    int idx = blockIdx.x * blockDim.x + threadIdx.x;
    if (idx < TC * NW) g_logits_char[idx] = 0.0f;
    if (idx < TS * NW) g_logits_syl[idx] = 0.0f;
}

__global__ void reinit_state_kernel() {
    int idx = blockIdx.x * blockDim.x + threadIdx.x;
    if (idx < 2 * NW * HH) { g_h[idx] = g_h0[idx]; g_c[idx] = 0.0f; }
}

// ---------------- generic tiled GEMM:  C = A[M,K] @ B[N,K]^T (+Add)(+b1+b2) ----------------
#define BMt 64
#define BNt 64
#define BKt 16

__global__ void __launch_bounds__(256) gemm64(
    const float* __restrict__ A, long long sAz,
    const float* __restrict__ B, long long sBz,
    const float* __restrict__ Add, long long sAddz, int ldAdd,
    const float* __restrict__ b1, const float* __restrict__ b2, long long sbz,
    float* __restrict__ C, long long sCz,
    int M, int N, int K) {
    __shared__ float As[BKt][BMt];
    __shared__ float Bs[BKt][BNt];
    long long z = blockIdx.z;
    A += z * sAz; B += z * sBz; C += z * sCz;
    if (Add) Add += z * sAddz;
    if (b1) b1 += z * sbz;
    if (b2) b2 += z * sbz;

    int tid = threadIdx.x;
    int bm = blockIdx.y * BMt, bn = blockIdx.x * BNt;
    int ar = tid >> 2, ak = (tid & 3) << 2;
    int ty = tid >> 4, tx = tid & 15;
    float acc[4][4] = {};

    for (int k0 = 0; k0 < K; k0 += BKt) {
        float4 av = *(const float4*)(A + (size_t)(bm + ar) * K + k0 + ak);
        float4 bv = *(const float4*)(B + (size_t)(bn + ar) * K + k0 + ak);
        As[ak + 0][ar] = av.x; As[ak + 1][ar] = av.y; As[ak + 2][ar] = av.z; As[ak + 3][ar] = av.w;
        Bs[ak + 0][ar] = bv.x; Bs[ak + 1][ar] = bv.y; Bs[ak + 2][ar] = bv.z; Bs[ak + 3][ar] = bv.w;
        __syncthreads();
#pragma unroll
        for (int kk = 0; kk < BKt; kk++) {
            float4 a = *(const float4*)&As[kk][ty << 2];
            float4 b = *(const float4*)&Bs[kk][tx << 2];
            float ar4[4] = {a.x, a.y, a.z, a.w};
            float br4[4] = {b.x, b.y, b.z, b.w};
#pragma unroll
            for (int i = 0; i < 4; i++)
#pragma unroll
                for (int j = 0; j < 4; j++)
                    acc[i][j] = fmaf(ar4[i], br4[j], acc[i][j]);
        }
        __syncthreads();
    }
#pragma unroll
    for (int i = 0; i < 4; i++) {
        int m = bm + (ty << 2) + i;
#pragma unroll
        for (int j = 0; j < 4; j++) {
            int n = bn + (tx << 2) + j;
            float v = acc[i][j];
            if (b1) v += b1[n];
            if (b2) v += b2[n];
            if (Add) v += Add[(size_t)m * ldAdd + n];
            C[(size_t)m * N + n] = v;
        }
    }
}

// ---------------- attention GEMM: logits[m] += sum_n tanh(A@B^T + ba)[m,n]*wv[n] ----------------
__global__ void __launch_bounds__(256) gemm_attn(
    const float* __restrict__ A, const float* __restrict__ B,
    const float* __restrict__ ba, const float* __restrict__ wv,
    float* __restrict__ logits, int M, int K) {
    __shared__ float As[BKt][BMt];
    __shared__ float Bs[BKt][BNt];
    int tid = threadIdx.x;
    int bm = blockIdx.y * BMt, bn = blockIdx.x * BNt;
    int ar = tid >> 2, ak = (tid & 3) << 2;
    int ty = tid >> 4, tx = tid & 15;
    float acc[4][4] = {};
    for (int k0 = 0; k0 < K; k0 += BKt) {
        float4 av = *(const float4*)(A + (size_t)(bm + ar) * K + k0 + ak);
        float4 bv = *(const float4*)(B + (size_t)(bn + ar) * K + k0 + ak);
        As[ak + 0][ar] = av.x; As[ak + 1][ar] = av.y; As[ak + 2][ar] = av.z; As[ak + 3][ar] = av.w;
        Bs[ak + 0][ar] = bv.x; Bs[ak + 1][ar] = bv.y; Bs[ak + 2][ar] = bv.z; Bs[ak + 3][ar] = bv.w;
        __syncthreads();
#pragma unroll
        for (int kk = 0; kk < BKt; kk++) {
            float4 a = *(const float4*)&As[kk][ty << 2];
            float4 b = *(const float4*)&Bs[kk][tx << 2];
            float ar4[4] = {a.x, a.y, a.z, a.w};
            float br4[4] = {b.x, b.y, b.z, b.w};
#pragma unroll
            for (int i = 0; i < 4; i++)
#pragma unroll
                for (int j = 0; j < 4; j++)
                    acc[i][j] = fmaf(ar4[i], br4[j], acc[i][j]);
        }
        __syncthreads();
    }
#pragma unroll
    for (int i = 0; i < 4; i++) {
        float s = 0.0f;
#pragma unroll
        for (int j = 0; j < 4; j++) {
            int n = bn + (tx << 2) + j;
            s += tanhfast(acc[i][j] + ba[n]) * wv[n];
        }
        s += __shfl_down_sync(0xffffffffu, s, 8, 16);
        s += __shfl_down_sync(0xffffffffu, s, 4, 16);
        s += __shfl_down_sync(0xffffffffu, s, 2, 16);
        s += __shfl_down_sync(0xffffffffu, s, 1, 16);
        if (tx == 0) atomicAdd(&logits[bm + (ty << 2) + i], s);
    }
}

// ---------------- LSTM pointwise: gates -> (h,c), writes out_seq[t][w][dir*HH+j] ----------------
__global__ void lstm_pointwise(float* __restrict__ out_seq, int s, int T) {
    int idx = blockIdx.x * blockDim.x + threadIdx.x;
    if (idx >= 2 * NW * HH) return;
    int j = idx % HH; int rest = idx / HH; int w = rest % NW; int dir = rest / NW;
    const float* g = g_gates + ((size_t)dir * NW + w) * G;
    float gi = sigf(g[j]);
    float gf = sigf(g[HH + j]);
    float gg = tanhfast(g[2 * HH + j]);
    float go = sigf(g[3 * HH + j]);
    float c = gf * g_c[idx] + gi * gg;
    float h = go * tanhfast(c);
    g_c[idx] = c; g_h[idx] = h;
    int t = dir ? (T - 1 - s) : s;
    out_seq[((size_t)t * NW + w) * Hd + dir * HH + j] = h;
}

// ---------------- attention softmax over t + context accumulation ----------------
__global__ void attn_ctx(const float* __restrict__ logits, const float* __restrict__ out_seq,
                         int T, int off) {
    int w = blockIdx.x;
    int tid = threadIdx.x;   // 256 = H
    __shared__ float p[16];
    if (tid == 0) {
        float l[16];
        float mx = -1e30f;
        for (int t = 0; t < T; t++) { l[t] = logits[t * NW + w]; mx = fmaxf(mx, l[t]); }
        float s = 0.0f;
        for (int t = 0; t < T; t++) { float e = __expf(l[t] - mx); p[t] = e; s += e; }
        float inv = 1.0f / s;
        for (int t = 0; t < T; t++) p[t] *= inv;
    }
    __syncthreads();
    float acc = 0.0f;
    for (int t = 0; t < T; t++)
        acc += p[t] * out_seq[((size_t)t * NW + w) * Hd + tid];
    g_xword[(size_t)w * XW + off + tid] = acc;
}

// ---------------- single-SM-per-direction word BiLSTM, packed f32x2 ----------------
// 2 CTAs (one per direction), 512 threads; thread n owns gate row n.
// Weights: k in [0,96) as 48 packed f32x2 pairs in registers; k in [96,128) in smem,
// loaded via asm volatile LDS.128 (prevents hoisting into registers).
// h loads: plain C++ ulonglong2 reads (ordered by __syncthreads).
#define WSM_CH 8   // 8 x 16B chunks = 32 smem k's per row
#define WLS_SMEM (WSM_CH * 512 * 16 + (HH + G) * 4 + 64)

__global__ void __launch_bounds__(512, 1) word_lstm_v3(const float* __restrict__ Whh) {
    extern __shared__ __align__(16) unsigned char sm_raw[];
    ulonglong2* wsm = (ulonglong2*)sm_raw;                 // [WSM_CH][512]
    float* hsm = (float*)(sm_raw + WSM_CH * 512 * 16);     // [HH]
    float* gsm = hsm + HH;                                 // [G]

    int dir = blockIdx.x;
    int n = threadIdx.x;
    const float* W = Whh + (size_t)dir * (G * HH) + (size_t)n * HH;

    // register half: k in [0,96) as 48 packed pairs
    unsigned long long wreg[48];
#pragma unroll
    for (int i = 0; i < 48; i++)
        wreg[i] = *reinterpret_cast<const unsigned long long*>(W + 2 * i);
    // smem half: k in [96,128), layout [chunk][n], 16B per entry
#pragma unroll
    for (int c = 0; c < WSM_CH; c++)
        wsm[c * 512 + n] = *reinterpret_cast<const ulonglong2*>(W + 96 + 4 * c);
    if (n < HH) hsm[n] = 0.0f;
    __syncthreads();

    uint32_t wsm_a = smem_u32(wsm);

    const float* ginp = g_gin_word + (size_t)dir * NW * G + n;
    int t = dir ? (NW - 1) : 0;
    int tstep = dir ? -1 : 1;
    float ginv = __ldg(ginp + (size_t)t * G);
    float creg = 0.0f;
    int gate = n >> 7;
    int j = n & 127;

    for (int s = 0; s < NW; s++, t += tstep) {
        // prefetch next step's gin (hidden under FMA work)
        float gnext = 0.0f;
        if (s + 1 < NW) gnext = __ldg(ginp + (size_t)(t + tstep) * G);

        unsigned long long acc0 = 0ull, acc1 = 0ull;   // packed {+0,+0}
#pragma unroll
        for (int i = 0; i < 24; i++) {                 // k in [4i, 4i+4), reg half
            ulonglong2 hv = *reinterpret_cast<const ulonglong2*>(hsm + 4 * i);
            fma2(acc0, wreg[2 * i], hv.x);
            fma2(acc1, wreg[2 * i + 1], hv.y);
        }
#pragma unroll
        for (int c = 0; c < WSM_CH; c++) {             // k in [96,128), smem half
            unsigned long long w0, w1;
            asm volatile("ld.shared.v2.u64 {%0,%1}, [%2];" : "=l"(w0), "=l"(w1)
                         : "r"(wsm_a + (uint32_t)(c * 512 + n) * 16u));
            ulonglong2 hv = *reinterpret_cast<const ulonglong2*>(hsm + 96 + 4 * c);
            fma2(acc0, w0, hv.x);
            fma2(acc1, w1, hv.y);
        }
        float g = upsum(acc0) + upsum(acc1) + ginv;
        ginv = gnext;
        // distributed activation: this thread's own gate value
        gsm[n] = (gate == 2) ? tanhfast(g) : sigf(g);
        __syncthreads();
        if (n < HH) {
            float gi = gsm[j], gf = gsm[HH + j], gg = gsm[2 * HH + j], go = gsm[3 * HH + j];
            creg = gf * creg + gi * gg;
            float hh = go * tanhfast(creg);
            hsm[j] = hh;
            g_outword[(size_t)t * Hd + dir * HH + j] = hh;
        }
        __syncthreads();
    }
}

// ---------------- final linear + log_softmax ----------------
__global__ void tag_kernel(const float* __restrict__ Wp, const float* __restrict__ bp,
                           const float* __restrict__ Wn, const float* __restrict__ bn,
                           float* __restrict__ out) {
    int w = blockIdx.x;
    int tid = threadIdx.x;  // 64
    __shared__ float o[Hd];
    __shared__ float sc[64];
    __shared__ float sc2[16];
    __shared__ float zp, zn;
    for (int d = tid; d < Hd; d += 64) o[d] = g_outword[(size_t)w * Hd + d];
    __syncthreads();
    if (tid < NPOS) {
        float s = bp[tid];
        for (int k = 0; k < Hd; k++) s = fmaf(o[k], Wp[tid * Hd + k], s);
        sc[tid] = s;
    }
    if (tid < NNER) {
        float s = bn[tid];
        for (int k = 0; k < Hd; k++) s = fmaf(o[k], Wn[tid * Hd + k], s);
        sc2[tid] = s;
    }
    __syncthreads();
    if (tid == 0) {
        float m = -1e30f;
        for (int i = 0; i < NPOS; i++) m = fmaxf(m, sc[i]);
        float s = 0.0f;
        for (int i = 0; i < NPOS; i++) s += __expf(sc[i] - m);
        zp = m + logf(s);
    }
    if (tid == 1) {
        float m = -1e30f;
        for (int i = 0; i < NNER; i++) m = fmaxf(m, sc2[i]);
        float s = 0.0f;
        for (int i = 0; i < NNER; i++) s += __expf(sc2[i] - m);
        zn = m + logf(s);
    }
    __syncthreads();
    if (tid < NPOS) out[(size_t)w * NPOS + tid] = sc[tid] - zp;
    if (tid < NNER) out[(size_t)NW * NPOS + (size_t)w * NNER + tid] = sc2[tid] - zn;
}

// ---------------- host launch ----------------
extern "C" void kernel_launch(void* const* d_in, const int* in_sizes, int n_in,
                              void* d_out, int out_size) {
    const int* word_seq = (const int*)d_in[0];
    const int* syl_seq  = (const int*)d_in[1];
    const int* char_seq = (const int*)d_in[2];
    const int* feat_seq = (const int*)d_in[3];
    const float* emb_char   = (const float*)d_in[4];
    const float* emb_syl    = (const float*)d_in[5];
    const float* emb_word   = (const float*)d_in[6];
    const float* emb_prefix = (const float*)d_in[7];
    const float* attn_c_W = (const float*)d_in[8];
    const float* attn_c_b = (const float*)d_in[9];
    const float* attn_c_w = (const float*)d_in[10];
    const float* attn_s_W = (const float*)d_in[11];
    const float* attn_s_b = (const float*)d_in[12];
    const float* attn_s_w = (const float*)d_in[13];
    const float* Wih_c = (const float*)d_in[14];
    const float* Whh_c = (const float*)d_in[15];
    const float* bih_c = (const float*)d_in[16];
    const float* bhh_c = (const float*)d_in[17];
    const float* Wih_s = (const float*)d_in[18];
    const float* Whh_s = (const float*)d_in[19];
    const float* bih_s = (const float*)d_in[20];
    const float* bhh_s = (const float*)d_in[21];
    const float* Wih_w = (const float*)d_in[22];
    const float* Whh_w = (const float*)d_in[23];
    const float* bih_w = (const float*)d_in[24];
    const float* bhh_w = (const float*)d_in[25];
    const float* W_pos = (const float*)d_in[26];
    const float* b_pos = (const float*)d_in[27];
    const float* W_ner = (const float*)d_in[28];
    const float* b_ner = (const float*)d_in[29];
    float* out = (float*)d_out;

    cudaFuncSetAttribute(word_lstm_v3, cudaFuncAttributeMaxDynamicSharedMemorySize, WLS_SMEM);

    float *p_x_char, *p_x_syl, *p_gin_char, *p_gin_syl, *p_gin_word;
    float *p_out_char, *p_out_syl, *p_h, *p_gates, *p_lg_char, *p_lg_syl, *p_xword;
    cudaGetSymbolAddress((void**)&p_x_char, g_x_char);
    cudaGetSymbolAddress((void**)&p_x_syl, g_x_syl);
    cudaGetSymbolAddress((void**)&p_gin_char, g_gin_char);
    cudaGetSymbolAddress((void**)&p_gin_syl, g_gin_syl);
    cudaGetSymbolAddress((void**)&p_gin_word, g_gin_word);
    cudaGetSymbolAddress((void**)&p_out_char, g_out_char);
    cudaGetSymbolAddress((void**)&p_out_syl, g_out_syl);
    cudaGetSymbolAddress((void**)&p_h, g_h);
    cudaGetSymbolAddress((void**)&p_gates, g_gates);
    cudaGetSymbolAddress((void**)&p_lg_char, g_logits_char);
    cudaGetSymbolAddress((void**)&p_lg_syl, g_logits_syl);
    cudaGetSymbolAddress((void**)&p_xword, g_xword);

    // 0) clear attention logits
    clear_logits_kernel<<<(TC * NW + 255) / 256, 256>>>();
    // 1) embedding gathers + h0/c0 init
    {
        int total = NW * TC * CD + NW * TS * SD + 2 * NW * HH + NW * WD;
        gather_kernel<<<(total + 255) / 256, 256>>>(word_seq, syl_seq, char_seq, feat_seq,
                                                    emb_char, emb_syl, emb_word, emb_prefix);
    }
    // 2) input projections (Gin = x @ Wih^T + bih + bhh) for char & syl, both dirs
    gemm64<<<dim3(G / 64, (NW * TC) / 64, 2), 256>>>(
        p_x_char, 0, Wih_c, (long long)G * CD,
        nullptr, 0, 0, bih_c, bhh_c, G,
        p_gin_char, (long long)NW * TC * G, NW * TC, G, CD);
    gemm64<<<dim3(G / 64, (NW * TS) / 64, 2), 256>>>(
        p_x_syl, 0, Wih_s, (long long)G * SD,
        nullptr, 0, 0, bih_s, bhh_s, G,
        p_gin_syl, (long long)NW * TS * G, NW * TS, G, SD);

    // 3) char BiLSTM recurrence (12 steps, both dirs per launch)
    for (int s = 0; s < TC; s++) {
        gemm64<<<dim3(G / 64, NW / 64, 2), 256>>>(
            p_h, (long long)NW * HH, Whh_c, (long long)G * HH,
            p_gin_char + (size_t)s * G,
            (long long)NW * TC * G + (long long)(TC - 1 - 2 * s) * G, TC * G,
            nullptr, nullptr, 0,
            p_gates, (long long)NW * G, NW, G, HH);
        lstm_pointwise<<<(2 * NW * HH + 255) / 256, 256>>>(p_out_char, s, TC);
    }
    // 4) char attention -> char_ctx into xword[:,256:512]
    gemm_attn<<<dim3(Hd / 64, (TC * NW) / 64), 256>>>(p_out_char, attn_c_W, attn_c_b, attn_c_w,
                                                      p_lg_char, TC * NW, Hd);
    attn_ctx<<<NW, Hd>>>(p_lg_char, p_out_char, TC, WD);

    // 5) syl BiLSTM (reinit state from h0, c=0)
    reinit_state_kernel<<<(2 * NW * HH + 255) / 256, 256>>>();
    for (int s = 0; s < TS; s++) {
        gemm64<<<dim3(G / 64, NW / 64, 2), 256>>>(
            p_h, (long long)NW * HH, Whh_s, (long long)G * HH,
            p_gin_syl + (size_t)s * G,
            (long long)NW * TS * G + (long long)(TS - 1 - 2 * s) * G, TS * G,
            nullptr, nullptr, 0,
            p_gates, (long long)NW * G, NW, G, HH);
        lstm_pointwise<<<(2 * NW * HH + 255) / 256, 256>>>(p_out_syl, s, TS);
    }
    // 6) syl attention -> syl_ctx into xword[:,512:768]
    gemm_attn<<<dim3(Hd / 64, (TS * NW) / 64), 256>>>(p_out_syl, attn_s_W, attn_s_b, attn_s_w,
                                                      p_lg_syl, TS * NW, Hd);
    attn_ctx<<<NW, Hd>>>(p_lg_syl, p_out_syl, TS, WD + Hd);

    // 7) word-level input projection
    gemm64<<<dim3(G / 64, NW / 64, 2), 256>>>(
        p_xword, 0, Wih_w, (long long)G * XW,
        nullptr, 0, 0, bih_w, bhh_w, G,
        p_gin_word, (long long)NW * G, NW, G, XW);

    // 8) sequential word BiLSTM (1 CTA per direction, packed f32x2)
    word_lstm_v3<<<2, 512, WLS_SMEM>>>(Whh_w);

    // 9) final linear + log_softmax -> [pos(2048x47) | ner(2048x13)]
    tag_kernel<<<NW, 64>>>(W_pos, b_pos, W_ner, b_ner, out);
}

// round 6
// speedup vs baseline: 1.7892x; 1.0648x over previous
#include <cuda_runtime.h>
#include <cuda_bf16.h>
#include <cstdint>

// ---------------- problem constants ----------------
#define NW   2048
#define TC   12
#define TS   4
#define CD   64
#define SD   64
#define WD   256
#define HH   128
#define Hd   256      // H
#define G    512      // 4*HH
#define XW   768      // WD + 2*H
#define NPOS 47
#define NNER 13

// ---------------- scratch (device globals; no allocs allowed) ----------------
__device__ float g_x_char[NW * TC * CD];
__device__ float g_x_syl[NW * TS * SD];
__device__ float g_gin_char[2 * NW * TC * G];
__device__ float g_gin_syl[2 * NW * TS * G];
__device__ float g_gin_word[2 * NW * G];
__device__ float g_out_char[TC * NW * Hd];
__device__ float g_out_syl[TS * NW * Hd];
__device__ float g_h[2 * NW * HH];
__device__ float g_c[2 * NW * HH];
__device__ float g_h0[2 * NW * HH];
__device__ float g_gates[2 * NW * G];
__device__ float g_logits_char[TC * NW];
__device__ float g_logits_syl[TS * NW];
__device__ float g_xword[NW * XW];
__device__ float g_outword[NW * Hd];

// ---------------- math helpers ----------------
__device__ __forceinline__ float sigf(float x) { return 1.0f / (1.0f + __expf(-x)); }
__device__ __forceinline__ float tanhfast(float x) {
    float t = __expf(-2.0f * fabsf(x));
    float r = (1.0f - t) / (1.0f + t);
    return copysignf(r, x);
}
__device__ __forceinline__ uint32_t smem_u32(const void* p) {
    uint32_t a;
    asm("{ .reg .u64 t; cvta.to.shared.u64 t, %1; cvt.u32.u64 %0, t; }" : "=r"(a) : "l"(p));
    return a;
}
__device__ __forceinline__ void fma2(unsigned long long& d, unsigned long long a, unsigned long long b) {
    asm("fma.rn.f32x2 %0, %1, %2, %0;" : "+l"(d) : "l"(a), "l"(b));
}
__device__ __forceinline__ float upsum(unsigned long long a) {
    return __uint_as_float((uint32_t)a) + __uint_as_float((uint32_t)(a >> 32));
}

// ---------------- gather: embeddings + h0 init ----------------
__global__ void gather_kernel(const int* __restrict__ word_seq, const int* __restrict__ syl_seq,
                              const int* __restrict__ char_seq, const int* __restrict__ feat_seq,
                              const float* __restrict__ emb_char, const float* __restrict__ emb_syl,
                              const float* __restrict__ emb_word, const float* __restrict__ emb_prefix) {
    int idx = blockIdx.x * blockDim.x + threadIdx.x;
    const int n0 = NW * TC * CD;
    const int n1 = n0 + NW * TS * SD;
    const int n2 = n1 + 2 * NW * HH;
    const int n3 = n2 + NW * WD;
    if (idx < n0) {
        int d = idx % CD; int rest = idx / CD; int t = rest % TC; int w = rest / TC;
        g_x_char[idx] = emb_char[char_seq[w * TC + t] * CD + d];
    } else if (idx < n1) {
        int i = idx - n0;
        int d = i % SD; int rest = i / SD; int t = rest % TS; int w = rest / TS;
        g_x_syl[i] = emb_syl[syl_seq[w * TS + t] * SD + d];
    } else if (idx < n2) {
        int i = idx - n1;             // [dir][w][j]
        int j = i % HH; int rest = i / HH; int w = rest % NW; int dir = rest / NW;
        float v = emb_prefix[feat_seq[w] * Hd + dir * HH + j];
        g_h0[i] = v; g_h[i] = v; g_c[i] = 0.0f;
    } else if (idx < n3) {
        int i = idx - n2;
        int d = i % WD; int w = i / WD;
        g_xword[w * XW + d] = emb_word[word_seq[w] * WD + d];
    }
}

__global__ void clear_logits_kernel() {
    int idx = blockIdx.x * blockDim.x + threadIdx.x;
    if (idx < TC * NW) g_logits_char[idx] = 0.0f;
    if (idx < TS * NW) g_logits_syl[idx] = 0.0f;
}

__global__ void reinit_state_kernel() {
    int idx = blockIdx.x * blockDim.x + threadIdx.x;
    if (idx < 2 * NW * HH) { g_h[idx] = g_h0[idx]; g_c[idx] = 0.0f; }
}

// ---------------- generic tiled GEMM:  C = A[M,K] @ B[N,K]^T (+Add)(+b1+b2) ----------------
#define BMt 64
#define BNt 64
#define BKt 16

__global__ void __launch_bounds__(256) gemm64(
    const float* __restrict__ A, long long sAz,
    const float* __restrict__ B, long long sBz,
    const float* __restrict__ Add, long long sAddz, int ldAdd,
    const float* __restrict__ b1, const float* __restrict__ b2, long long sbz,
    float* __restrict__ C, long long sCz,
    int M, int N, int K) {
    __shared__ float As[BKt][BMt];
    __shared__ float Bs[BKt][BNt];
    long long z = blockIdx.z;
    A += z * sAz; B += z * sBz; C += z * sCz;
    if (Add) Add += z * sAddz;
    if (b1) b1 += z * sbz;
    if (b2) b2 += z * sbz;

    int tid = threadIdx.x;
    int bm = blockIdx.y * BMt, bn = blockIdx.x * BNt;
    int ar = tid >> 2, ak = (tid & 3) << 2;
    int ty = tid >> 4, tx = tid & 15;
    float acc[4][4] = {};

    for (int k0 = 0; k0 < K; k0 += BKt) {
        float4 av = *(const float4*)(A + (size_t)(bm + ar) * K + k0 + ak);
        float4 bv = *(const float4*)(B + (size_t)(bn + ar) * K + k0 + ak);
        As[ak + 0][ar] = av.x; As[ak + 1][ar] = av.y; As[ak + 2][ar] = av.z; As[ak + 3][ar] = av.w;
        Bs[ak + 0][ar] = bv.x; Bs[ak + 1][ar] = bv.y; Bs[ak + 2][ar] = bv.z; Bs[ak + 3][ar] = bv.w;
        __syncthreads();
#pragma unroll
        for (int kk = 0; kk < BKt; kk++) {
            float4 a = *(const float4*)&As[kk][ty << 2];
            float4 b = *(const float4*)&Bs[kk][tx << 2];
            float ar4[4] = {a.x, a.y, a.z, a.w};
            float br4[4] = {b.x, b.y, b.z, b.w};
#pragma unroll
            for (int i = 0; i < 4; i++)
#pragma unroll
                for (int j = 0; j < 4; j++)
                    acc[i][j] = fmaf(ar4[i], br4[j], acc[i][j]);
        }
        __syncthreads();
    }
#pragma unroll
    for (int i = 0; i < 4; i++) {
        int m = bm + (ty << 2) + i;
#pragma unroll
        for (int j = 0; j < 4; j++) {
            int n = bn + (tx << 2) + j;
            float v = acc[i][j];
            if (b1) v += b1[n];
            if (b2) v += b2[n];
            if (Add) v += Add[(size_t)m * ldAdd + n];
            C[(size_t)m * N + n] = v;
        }
    }
}

// ---------------- attention GEMM: logits[m] += sum_n tanh(A@B^T + ba)[m,n]*wv[n] ----------------
__global__ void __launch_bounds__(256) gemm_attn(
    const float* __restrict__ A, const float* __restrict__ B,
    const float* __restrict__ ba, const float* __restrict__ wv,
    float* __restrict__ logits, int M, int K) {
    __shared__ float As[BKt][BMt];
    __shared__ float Bs[BKt][BNt];
    int tid = threadIdx.x;
    int bm = blockIdx.y * BMt, bn = blockIdx.x * BNt;
    int ar = tid >> 2, ak = (tid & 3) << 2;
    int ty = tid >> 4, tx = tid & 15;
    float acc[4][4] = {};
    for (int k0 = 0; k0 < K; k0 += BKt) {
        float4 av = *(const float4*)(A + (size_t)(bm + ar) * K + k0 + ak);
        float4 bv = *(const float4*)(B + (size_t)(bn + ar) * K + k0 + ak);
        As[ak + 0][ar] = av.x; As[ak + 1][ar] = av.y; As[ak + 2][ar] = av.z; As[ak + 3][ar] = av.w;
        Bs[ak + 0][ar] = bv.x; Bs[ak + 1][ar] = bv.y; Bs[ak + 2][ar] = bv.z; Bs[ak + 3][ar] = bv.w;
        __syncthreads();
#pragma unroll
        for (int kk = 0; kk < BKt; kk++) {
            float4 a = *(const float4*)&As[kk][ty << 2];
            float4 b = *(const float4*)&Bs[kk][tx << 2];
            float ar4[4] = {a.x, a.y, a.z, a.w};
            float br4[4] = {b.x, b.y, b.z, b.w};
#pragma unroll
            for (int i = 0; i < 4; i++)
#pragma unroll
                for (int j = 0; j < 4; j++)
                    acc[i][j] = fmaf(ar4[i], br4[j], acc[i][j]);
        }
        __syncthreads();
    }
#pragma unroll
    for (int i = 0; i < 4; i++) {
        float s = 0.0f;
#pragma unroll
        for (int j = 0; j < 4; j++) {
            int n = bn + (tx << 2) + j;
            s += tanhfast(acc[i][j] + ba[n]) * wv[n];
        }
        s += __shfl_down_sync(0xffffffffu, s, 8, 16);
        s += __shfl_down_sync(0xffffffffu, s, 4, 16);
        s += __shfl_down_sync(0xffffffffu, s, 2, 16);
        s += __shfl_down_sync(0xffffffffu, s, 1, 16);
        if (tx == 0) atomicAdd(&logits[bm + (ty << 2) + i], s);
    }
}

// ---------------- LSTM pointwise: gates -> (h,c), writes out_seq[t][w][dir*HH+j] ----------------
__global__ void lstm_pointwise(float* __restrict__ out_seq, int s, int T) {
    int idx = blockIdx.x * blockDim.x + threadIdx.x;
    if (idx >= 2 * NW * HH) return;
    int j = idx % HH; int rest = idx / HH; int w = rest % NW; int dir = rest / NW;
    const float* g = g_gates + ((size_t)dir * NW + w) * G;
    float gi = sigf(g[j]);
    float gf = sigf(g[HH + j]);
    float gg = tanhfast(g[2 * HH + j]);
    float go = sigf(g[3 * HH + j]);
    float c = gf * g_c[idx] + gi * gg;
    float h = go * tanhfast(c);
    g_c[idx] = c; g_h[idx] = h;
    int t = dir ? (T - 1 - s) : s;
    out_seq[((size_t)t * NW + w) * Hd + dir * HH + j] = h;
}

// ---------------- attention softmax over t + context accumulation ----------------
__global__ void attn_ctx(const float* __restrict__ logits, const float* __restrict__ out_seq,
                         int T, int off) {
    int w = blockIdx.x;
    int tid = threadIdx.x;   // 256 = H
    __shared__ float p[16];
    if (tid == 0) {
        float l[16];
        float mx = -1e30f;
        for (int t = 0; t < T; t++) { l[t] = logits[t * NW + w]; mx = fmaxf(mx, l[t]); }
        float s = 0.0f;
        for (int t = 0; t < T; t++) { float e = __expf(l[t] - mx); p[t] = e; s += e; }
        float inv = 1.0f / s;
        for (int t = 0; t < T; t++) p[t] *= inv;
    }
    __syncthreads();
    float acc = 0.0f;
    for (int t = 0; t < T; t++)
        acc += p[t] * out_seq[((size_t)t * NW + w) * Hd + tid];
    g_xword[(size_t)w * XW + off + tid] = acc;
}

// ---------------- single-SM-per-direction word BiLSTM, k-split f32x2 ----------------
// 2 CTAs (one per direction), 512 threads = 128 j-outputs x 4 k-quarters.
// Thread (j,kq) computes partial dots for ALL 4 gates over its 32-k quarter:
// 24 k in registers (12 packed f32x2 per gate, slot i <-> gate kq^i), 8 k in smem.
// 3-shfl butterfly gives each lane its OWN gate total; distributed activations;
// 3 shfl gather -> kq0 does c/h update. One __syncthreads per step, double-buffered h.
// hsm quarters padded to 36 floats so the 4 kq groups hit disjoint banks.
#define HQ 36                     // padded quarter stride (floats)
#define HBUF (4 * HQ)             // one h buffer (144 floats)
#define WLS_SMEM (8 * 512 * 16 + 2 * HBUF * 4 + 64)

__global__ void __launch_bounds__(512, 1) word_lstm_v4(const float* __restrict__ Whh) {
    extern __shared__ __align__(16) unsigned char sm_raw[];
    ulonglong2* wsm = (ulonglong2*)sm_raw;             // [8][512] (slot*2+chunk, tid)
    float* hsm = (float*)(sm_raw + 8 * 512 * 16);      // [2][HBUF]

    int dir = blockIdx.x;
    int tid = threadIdx.x;
    int j  = tid >> 2;
    int kq = tid & 3;

    const float* Wd = Whh + (size_t)dir * (G * HH);
    // slot i corresponds to gate g = kq ^ i (rotation removes dynamic indexing later)
    unsigned long long wreg[48];
#pragma unroll
    for (int i = 0; i < 4; i++) {
        int g = kq ^ i;
        const float* Wr = Wd + (size_t)(g * HH + j) * HH + kq * 32;
#pragma unroll
        for (int m = 0; m < 12; m++)
            wreg[i * 12 + m] = *(const unsigned long long*)(Wr + 2 * m);
        wsm[(i * 2 + 0) * 512 + tid] = *(const ulonglong2*)(Wr + 24);
        wsm[(i * 2 + 1) * 512 + tid] = *(const ulonglong2*)(Wr + 28);
    }
    if (tid < 2 * HBUF) hsm[tid] = 0.0f;
    __syncthreads();

    uint32_t wsm_a = smem_u32(wsm) + (uint32_t)tid * 16u;
    const float* gcur = g_gin_word + (size_t)dir * NW * G + kq * HH + j;
    int t0 = dir ? (NW - 1) : 0;
    long long tstep = dir ? -1 : 1;
    long long gstride = tstep * G;
    gcur += (size_t)t0 * G;
    float ginv = __ldg(gcur);
    float* outp = g_outword + (size_t)t0 * Hd + dir * HH + j;
    long long ostride = tstep * Hd;
    float creg = 0.0f;

    for (int s = 0; s < NW; s++) {
        const float* hs = hsm + (s & 1) * HBUF + kq * HQ;
        float gnext = 0.0f;
        if (s + 1 < NW) gnext = __ldg(gcur + gstride);
        gcur += gstride;

        unsigned long long a0, a1, a2, a3;
        {
            ulonglong2 hv = *(const ulonglong2*)(hs);
            asm("mul.rn.f32x2 %0, %1, %2;" : "=l"(a0) : "l"(wreg[0]),  "l"(hv.x));
            asm("mul.rn.f32x2 %0, %1, %2;" : "=l"(a1) : "l"(wreg[12]), "l"(hv.x));
            asm("mul.rn.f32x2 %0, %1, %2;" : "=l"(a2) : "l"(wreg[24]), "l"(hv.x));
            asm("mul.rn.f32x2 %0, %1, %2;" : "=l"(a3) : "l"(wreg[36]), "l"(hv.x));
            fma2(a0, wreg[1],  hv.y);
            fma2(a1, wreg[13], hv.y);
            fma2(a2, wreg[25], hv.y);
            fma2(a3, wreg[37], hv.y);
        }
#pragma unroll
        for (int ch = 1; ch < 6; ch++) {
            ulonglong2 hv = *(const ulonglong2*)(hs + 4 * ch);
            fma2(a0, wreg[2 * ch],      hv.x); fma2(a0, wreg[2 * ch + 1],      hv.y);
            fma2(a1, wreg[12 + 2 * ch], hv.x); fma2(a1, wreg[12 + 2 * ch + 1], hv.y);
            fma2(a2, wreg[24 + 2 * ch], hv.x); fma2(a2, wreg[24 + 2 * ch + 1], hv.y);
            fma2(a3, wreg[36 + 2 * ch], hv.x); fma2(a3, wreg[36 + 2 * ch + 1], hv.y);
        }
#pragma unroll
        for (int c = 0; c < 2; c++) {
            ulonglong2 hv = *(const ulonglong2*)(hs + 24 + 4 * c);
            unsigned long long w0, w1;
            asm volatile("ld.shared.v2.u64 {%0,%1}, [%2];" : "=l"(w0), "=l"(w1)
                         : "r"(wsm_a + (uint32_t)((0 * 2 + c) * 512 * 16)));
            fma2(a0, w0, hv.x); fma2(a0, w1, hv.y);
            asm volatile("ld.shared.v2.u64 {%0,%1}, [%2];" : "=l"(w0), "=l"(w1)
                         : "r"(wsm_a + (uint32_t)((1 * 2 + c) * 512 * 16)));
            fma2(a1, w0, hv.x); fma2(a1, w1, hv.y);
            asm volatile("ld.shared.v2.u64 {%0,%1}, [%2];" : "=l"(w0), "=l"(w1)
                         : "r"(wsm_a + (uint32_t)((2 * 2 + c) * 512 * 16)));
            fma2(a2, w0, hv.x); fma2(a2, w1, hv.y);
            asm volatile("ld.shared.v2.u64 {%0,%1}, [%2];" : "=l"(w0), "=l"(w1)
                         : "r"(wsm_a + (uint32_t)((3 * 2 + c) * 512 * 16)));
            fma2(a3, w0, hv.x); fma2(a3, w1, hv.y);
        }
        float p0 = upsum(a0), p1 = upsum(a1), p2 = upsum(a2), p3 = upsum(a3);
        // 3-shfl butterfly: each lane ends with the full sum of ITS gate (slot-rotated)
        float s0 = p0 + __shfl_xor_sync(0xffffffffu, p1, 1, 4);
        float s2 = p2 + __shfl_xor_sync(0xffffffffu, p3, 1, 4);
        float tot = s0 + __shfl_xor_sync(0xffffffffu, s2, 2, 4) + ginv;
        ginv = gnext;
        // distributed activation (gate kq; gate 2 = cell input uses tanh)
        float act = (kq == 2) ? tanhfast(tot) : sigf(tot);
        float af = __shfl_sync(0xffffffffu, act, 1, 4);
        float ag = __shfl_sync(0xffffffffu, act, 2, 4);
        float ao = __shfl_sync(0xffffffffu, act, 3, 4);
        if (kq == 0) {
            creg = af * creg + act * ag;
            float hh = ao * tanhfast(creg);
            float* hw = hsm + ((s + 1) & 1) * HBUF;
            hw[(j >> 5) * HQ + (j & 31)] = hh;
            *outp = hh;
        }
        outp += ostride;
        __syncthreads();
    }
}

// ---------------- final linear + log_softmax ----------------
__global__ void tag_kernel(const float* __restrict__ Wp, const float* __restrict__ bp,
                           const float* __restrict__ Wn, const float* __restrict__ bn,
                           float* __restrict__ out) {
    int w = blockIdx.x;
    int tid = threadIdx.x;  // 64
    __shared__ float o[Hd];
    __shared__ float sc[64];
    __shared__ float sc2[16];
    __shared__ float zp, zn;
    for (int d = tid; d < Hd; d += 64) o[d] = g_outword[(size_t)w * Hd + d];
    __syncthreads();
    if (tid < NPOS) {
        float s = bp[tid];
        for (int k = 0; k < Hd; k++) s = fmaf(o[k], Wp[tid * Hd + k], s);
        sc[tid] = s;
    }
    if (tid < NNER) {
        float s = bn[tid];
        for (int k = 0; k < Hd; k++) s = fmaf(o[k], Wn[tid * Hd + k], s);
        sc2[tid] = s;
    }
    __syncthreads();
    if (tid == 0) {
        float m = -1e30f;
        for (int i = 0; i < NPOS; i++) m = fmaxf(m, sc[i]);
        float s = 0.0f;
        for (int i = 0; i < NPOS; i++) s += __expf(sc[i] - m);
        zp = m + logf(s);
    }
    if (tid == 1) {
        float m = -1e30f;
        for (int i = 0; i < NNER; i++) m = fmaxf(m, sc2[i]);
        float s = 0.0f;
        for (int i = 0; i < NNER; i++) s += __expf(sc2[i] - m);
        zn = m + logf(s);
    }
    __syncthreads();
    if (tid < NPOS) out[(size_t)w * NPOS + tid] = sc[tid] - zp;
    if (tid < NNER) out[(size_t)NW * NPOS + (size_t)w * NNER + tid] = sc2[tid] - zn;
}

// ---------------- host launch ----------------
extern "C" void kernel_launch(void* const* d_in, const int* in_sizes, int n_in,
                              void* d_out, int out_size) {
    const int* word_seq = (const int*)d_in[0];
    const int* syl_seq  = (const int*)d_in[1];
    const int* char_seq = (const int*)d_in[2];
    const int* feat_seq = (const int*)d_in[3];
    const float* emb_char   = (const float*)d_in[4];
    const float* emb_syl    = (const float*)d_in[5];
    const float* emb_word   = (const float*)d_in[6];
    const float* emb_prefix = (const float*)d_in[7];
    const float* attn_c_W = (const float*)d_in[8];
    const float* attn_c_b = (const float*)d_in[9];
    const float* attn_c_w = (const float*)d_in[10];
    const float* attn_s_W = (const float*)d_in[11];
    const float* attn_s_b = (const float*)d_in[12];
    const float* attn_s_w = (const float*)d_in[13];
    const float* Wih_c = (const float*)d_in[14];
    const float* Whh_c = (const float*)d_in[15];
    const float* bih_c = (const float*)d_in[16];
    const float* bhh_c = (const float*)d_in[17];
    const float* Wih_s = (const float*)d_in[18];
    const float* Whh_s = (const float*)d_in[19];
    const float* bih_s = (const float*)d_in[20];
    const float* bhh_s = (const float*)d_in[21];
    const float* Wih_w = (const float*)d_in[22];
    const float* Whh_w = (const float*)d_in[23];
    const float* bih_w = (const float*)d_in[24];
    const float* bhh_w = (const float*)d_in[25];
    const float* W_pos = (const float*)d_in[26];
    const float* b_pos = (const float*)d_in[27];
    const float* W_ner = (const float*)d_in[28];
    const float* b_ner = (const float*)d_in[29];
    float* out = (float*)d_out;

    cudaFuncSetAttribute(word_lstm_v4, cudaFuncAttributeMaxDynamicSharedMemorySize, WLS_SMEM);

    float *p_x_char, *p_x_syl, *p_gin_char, *p_gin_syl, *p_gin_word;
    float *p_out_char, *p_out_syl, *p_h, *p_gates, *p_lg_char, *p_lg_syl, *p_xword;
    cudaGetSymbolAddress((void**)&p_x_char, g_x_char);
    cudaGetSymbolAddress((void**)&p_x_syl, g_x_syl);
    cudaGetSymbolAddress((void**)&p_gin_char, g_gin_char);
    cudaGetSymbolAddress((void**)&p_gin_syl, g_gin_syl);
    cudaGetSymbolAddress((void**)&p_gin_word, g_gin_word);
    cudaGetSymbolAddress((void**)&p_out_char, g_out_char);
    cudaGetSymbolAddress((void**)&p_out_syl, g_out_syl);
    cudaGetSymbolAddress((void**)&p_h, g_h);
    cudaGetSymbolAddress((void**)&p_gates, g_gates);
    cudaGetSymbolAddress((void**)&p_lg_char, g_logits_char);
    cudaGetSymbolAddress((void**)&p_lg_syl, g_logits_syl);
    cudaGetSymbolAddress((void**)&p_xword, g_xword);

    // 0) clear attention logits
    clear_logits_kernel<<<(TC * NW + 255) / 256, 256>>>();
    // 1) embedding gathers + h0/c0 init
    {
        int total = NW * TC * CD + NW * TS * SD + 2 * NW * HH + NW * WD;
        gather_kernel<<<(total + 255) / 256, 256>>>(word_seq, syl_seq, char_seq, feat_seq,
                                                    emb_char, emb_syl, emb_word, emb_prefix);
    }
    // 2) input projections (Gin = x @ Wih^T + bih + bhh) for char & syl, both dirs
    gemm64<<<dim3(G / 64, (NW * TC) / 64, 2), 256>>>(
        p_x_char, 0, Wih_c, (long long)G * CD,
        nullptr, 0, 0, bih_c, bhh_c, G,
        p_gin_char, (long long)NW * TC * G, NW * TC, G, CD);
    gemm64<<<dim3(G / 64, (NW * TS) / 64, 2), 256>>>(
        p_x_syl, 0, Wih_s, (long long)G * SD,
        nullptr, 0, 0, bih_s, bhh_s, G,
        p_gin_syl, (long long)NW * TS * G, NW * TS, G, SD);

    // 3) char BiLSTM recurrence (12 steps, both dirs per launch)
    for (int s = 0; s < TC; s++) {
        gemm64<<<dim3(G / 64, NW / 64, 2), 256>>>(
            p_h, (long long)NW * HH, Whh_c, (long long)G * HH,
            p_gin_char + (size_t)s * G,
            (long long)NW * TC * G + (long long)(TC - 1 - 2 * s) * G, TC * G,
            nullptr, nullptr, 0,
            p_gates, (long long)NW * G, NW, G, HH);
        lstm_pointwise<<<(2 * NW * HH + 255) / 256, 256>>>(p_out_char, s, TC);
    }
    // 4) char attention -> char_ctx into xword[:,256:512]
    gemm_attn<<<dim3(Hd / 64, (TC * NW) / 64), 256>>>(p_out_char, attn_c_W, attn_c_b, attn_c_w,
                                                      p_lg_char, TC * NW, Hd);
    attn_ctx<<<NW, Hd>>>(p_lg_char, p_out_char, TC, WD);

    // 5) syl BiLSTM (reinit state from h0, c=0)
    reinit_state_kernel<<<(2 * NW * HH + 255) / 256, 256>>>();
    for (int s = 0; s < TS; s++) {
        gemm64<<<dim3(G / 64, NW / 64, 2), 256>>>(
            p_h, (long long)NW * HH, Whh_s, (long long)G * HH,
            p_gin_syl + (size_t)s * G,
            (long long)NW * TS * G + (long long)(TS - 1 - 2 * s) * G, TS * G,
            nullptr, nullptr, 0,
            p_gates, (long long)NW * G, NW, G, HH);
        lstm_pointwise<<<(2 * NW * HH + 255) / 256, 256>>>(p_out_syl, s, TS);
    }
    // 6) syl attention -> syl_ctx into xword[:,512:768]
    gemm_attn<<<dim3(Hd / 64, (TS * NW) / 64), 256>>>(p_out_syl, attn_s_W, attn_s_b, attn_s_w,
                                                      p_lg_syl, TS * NW, Hd);
    attn_ctx<<<NW, Hd>>>(p_lg_syl, p_out_syl, TS, WD + Hd);

    // 7) word-level input projection
    gemm64<<<dim3(G / 64, NW / 64, 2), 256>>>(
        p_xword, 0, Wih_w, (long long)G * XW,
        nullptr, 0, 0, bih_w, bhh_w, G,
        p_gin_word, (long long)NW * G, NW, G, XW);

    // 8) sequential word BiLSTM (1 CTA per direction, k-split f32x2)
    word_lstm_v4<<<2, 512, WLS_SMEM>>>(Whh_w);

    // 9) final linear + log_softmax -> [pos(2048x47) | ner(2048x13)]
    tag_kernel<<<NW, 64>>>(W_pos, b_pos, W_ner, b_ner, out);
}